// round 14
// baseline (speedup 1.0000x reference)
#include <cuda_runtime.h>
#include <cuda_fp16.h>
#include <stdint.h>
#include <math.h>

#define BB 2
#define LL 192
#define DD 384
#define HH 8
#define DHH 48
#define NN 384
#define EPSF 1e-5f

// Scratch (allocation-free rule: __device__ globals)
__device__ float g_xn[BB * LL * DD];   // layernormed x (fp32, for v-proj)
__device__ __half g_xh[BB * LL * DD];  // xn fp16
__device__ float g_v[BB * LL * NN];    // v projection
__device__ float g_dots[BB * HH * LL * LL];  // attention logits -> probs (in place)
__device__ float g_ao[BB * LL * NN];         // attn @ v, head-merged

// ======================= baseline-PTX tensor helpers (sm_80+) =======================
__device__ __forceinline__ uint32_t smem_u32(const void* p) {
    uint32_t a;
    asm("{ .reg .u64 t; cvta.to.shared.u64 t, %1; cvt.u32.u64 %0, t; }" : "=r"(a) : "l"(p));
    return a;
}
__device__ __forceinline__ void ldsm4(uint32_t addr, uint32_t& r0, uint32_t& r1, uint32_t& r2,
                                      uint32_t& r3) {
    asm volatile("ldmatrix.sync.aligned.m8n8.x4.shared.b16 {%0,%1,%2,%3}, [%4];"
                 : "=r"(r0), "=r"(r1), "=r"(r2), "=r"(r3)
                 : "r"(addr));
}
__device__ __forceinline__ void mma_f16(float* c, uint32_t a0, uint32_t a1, uint32_t a2,
                                        uint32_t a3, uint32_t b0, uint32_t b1) {
    asm volatile(
        "mma.sync.aligned.m16n8k16.row.col.f32.f16.f16.f32 "
        "{%0,%1,%2,%3}, {%4,%5,%6,%7}, {%8,%9}, {%0,%1,%2,%3};"
        : "+f"(c[0]), "+f"(c[1]), "+f"(c[2]), "+f"(c[3])
        : "r"(a0), "r"(a1), "r"(a2), "r"(a3), "r"(b0), "r"(b1));
}
__device__ __forceinline__ void cp16(uint32_t dst, const void* src, int src_bytes) {
    asm volatile("cp.async.cg.shared.global [%0], [%1], 16, %2;" ::"r"(dst), "l"(src),
                 "r"(src_bytes)
                 : "memory");
}
__device__ __forceinline__ void cp_wait_all() {
    asm volatile("cp.async.wait_all;" ::: "memory");
}

// ======================= LayerNorm (+ fp16 precompute) =======================
__global__ void __launch_bounds__(128) ln_kernel(const float* __restrict__ x,
                                                 const float* __restrict__ gamma,
                                                 const float* __restrict__ beta) {
    const int row = blockIdx.x;
    const int tid = threadIdx.x;
    const float* xr = x + (size_t)row * DD;
    float s = 0.f, s2 = 0.f;
    for (int c = tid; c < DD; c += 128) {
        float t = xr[c];
        s += t;
        s2 += t * t;
    }
    for (int o = 16; o; o >>= 1) {
        s += __shfl_xor_sync(0xffffffffu, s, o);
        s2 += __shfl_xor_sync(0xffffffffu, s2, o);
    }
    __shared__ float sh[8];
    const int w = tid >> 5;
    if ((tid & 31) == 0) {
        sh[w] = s;
        sh[4 + w] = s2;
    }
    __syncthreads();
    s = sh[0] + sh[1] + sh[2] + sh[3];
    s2 = sh[4] + sh[5] + sh[6] + sh[7];
    const float mu = s * (1.0f / DD);
    const float var = s2 * (1.0f / DD) - mu * mu;
    const float rstd = rsqrtf(var + EPSF);
    for (int c = tid; c < DD; c += 128) {
        const float v = (xr[c] - mu) * rstd * gamma[c] + beta[c];
        g_xn[(size_t)row * DD + c] = v;
        g_xh[(size_t)row * DD + c] = __float2half_rn(v);
    }
}

// ======================= small fp32 GEMM, 32x32 tiles (v / o projections) =======================
__global__ void __launch_bounds__(128) gemm32_kernel(const float* __restrict__ A,
                                                     const float* __restrict__ Bw,
                                                     const float* __restrict__ bias,
                                                     float* __restrict__ C, int has_bias) {
    __shared__ float As[32][33];
    __shared__ float Bs[32][36];
    const int bm = blockIdx.y * 32, bn = blockIdx.x * 32;
    const int tid = threadIdx.x;
    const int tx = tid & 7, ty = tid >> 3;  // 8 x 4 cols, 16 x 2 rows
    float acc[2][4] = {};
    for (int k0 = 0; k0 < 384; k0 += 32) {
#pragma unroll
        for (int idx = tid; idx < 1024; idx += 128) {
            const int m = idx >> 5, kk = idx & 31;
            As[kk][m] = A[(size_t)(bm + m) * 384 + k0 + kk];
        }
#pragma unroll
        for (int idx = tid; idx < 1024; idx += 128) {
            const int kk = idx >> 5, n = idx & 31;
            Bs[kk][n] = Bw[(size_t)(k0 + kk) * 384 + bn + n];
        }
        __syncthreads();
#pragma unroll
        for (int kk = 0; kk < 32; ++kk) {
            const float a0 = As[kk][ty * 2], a1 = As[kk][ty * 2 + 1];
            const float4 b4 = *(const float4*)&Bs[kk][tx * 4];
            const float b[4] = {b4.x, b4.y, b4.z, b4.w};
#pragma unroll
            for (int j = 0; j < 4; ++j) {
                acc[0][j] += a0 * b[j];
                acc[1][j] += a1 * b[j];
            }
        }
        __syncthreads();
    }
#pragma unroll
    for (int i = 0; i < 2; ++i)
#pragma unroll
        for (int j = 0; j < 4; ++j) {
            const int row = bm + ty * 2 + i, col = bn + tx * 4 + j;
            float o = acc[i][j];
            if (has_bias) o += bias[col];
            C[(size_t)row * 384 + col] = o;
        }
}

// ======================= dots via mma.sync HMMA (fp16 x fp16, 1 product) ==========
// CTA = (r = blockIdx.y, 128-row tile = blockIdx.x). Logical row u in [0, 2*(L-r)):
// b = u>=L-r, t = u-b*(L-r). Q row = xn[b,r+t] @ u_q[L-1-r], K row = xn[b,t] @ u_k[r].
// Both x and W in fp16 (independent ~2^-11 rounding -> ~1e-4 final rel err, 9x margin).
#define MT 128
#define KC 32
#define ASTRIDE 80   // 64B row + 16B pad: 16B-aligned stride, conflict-free ldmatrix
#define A_ARR 10240  // 128*80
#define A_BUF 20480  // 2 arrays (QH, KH)
#define W_ARR 3840   // 48*80
#define W_BUF 7680   // 2 arrays (WQH, WKH)
#define W_BASE 40960  // 2*A_BUF
#define SM_TOTAL (W_BASE + 2 * W_BUF)  // 56320 bytes

#define AQH 0
#define AKH 10240
#define WQH 0
#define WKH 3840

__device__ __forceinline__ void stage_A(uint32_t abase, int m0, int nbr, int tot, int r, int k0,
                                        int tid) {
    const char* xh = (const char*)g_xh;
#pragma unroll
    for (int q = tid; q < 512; q += 256) {
        const int m = q >> 2, seg = q & 3;
        const int u = m0 + m;
        const int valid = (u < tot) ? 16 : 0;
        int b = (u >= nbr) ? 1 : 0;
        int t = u - b * nbr;
        if (!valid) {
            b = 0;
            t = 0;
        }
        const int rowq = b * LL + r + t;
        const int rowk = b * LL + t;
        const size_t boff = (size_t)k0 * 2 + seg * 16;
        const uint32_t so = abase + m * ASTRIDE + seg * 16;
        cp16(so + AQH, xh + (size_t)rowq * (DD * 2) + boff, valid);
        cp16(so + AKH, xh + (size_t)rowk * (DD * 2) + boff, valid);
    }
}

// W prefetch: 3 tasks/thread, each task = (n, k2) pair; loads 2 consecutive-k fp32 for Q and K.
__device__ __forceinline__ void loadW(const float* __restrict__ Wq, const float* __restrict__ Wk,
                                      int n0, int k0, int tid, float* wq0, float* wq1, float* wk0,
                                      float* wk1) {
#pragma unroll
    for (int s = 0; s < 3; ++s) {
        const int idx = tid + s * 256;  // < 768
        const int k2 = idx / 48;
        const int n = idx - k2 * 48;
        const size_t g0 = (size_t)(k0 + 2 * k2) * NN + n0 + n;
        wq0[s] = Wq[g0];
        wq1[s] = Wq[g0 + NN];
        wk0[s] = Wk[g0];
        wk1[s] = Wk[g0 + NN];
    }
}

__device__ __forceinline__ void storeW(char* smem, uint32_t wrel, int tid, const float* wq0,
                                       const float* wq1, const float* wk0, const float* wk1) {
#pragma unroll
    for (int s = 0; s < 3; ++s) {
        const int idx = tid + s * 256;
        const int k2 = idx / 48;
        const int n = idx - k2 * 48;
        __half2 qh, kh;
        qh.x = __float2half_rn(wq0[s]);
        qh.y = __float2half_rn(wq1[s]);
        kh.x = __float2half_rn(wk0[s]);
        kh.y = __float2half_rn(wk1[s]);
        const uint32_t so = wrel + n * ASTRIDE + k2 * 4;
        *(uint32_t*)(smem + so + WQH) = *(uint32_t*)&qh;
        *(uint32_t*)(smem + so + WKH) = *(uint32_t*)&kh;
    }
}

__global__ void __launch_bounds__(256, 2) dots_mma_kernel(const float* __restrict__ uq,
                                                          const float* __restrict__ uk) {
    const int r = blockIdx.y;
    const int m0 = blockIdx.x * MT;
    const int nbr = LL - r;
    const int tot = 2 * nbr;
    if (m0 >= tot) return;

    extern __shared__ char smem[];
    const uint32_t sb = smem_u32(smem);
    const int tid = threadIdx.x;
    const int wid = tid >> 5, lane = tid & 31;

    const float* __restrict__ Wq = uq + (size_t)(LL - 1 - r) * DD * NN;
    const float* __restrict__ Wk = uk + (size_t)r * DD * NN;

    // prologue: stage it=0 into buffer 0
    stage_A(sb, m0, nbr, tot, r, 0, tid);
    {
        float q0[3], q1[3], k0v[3], k1v[3];
        loadW(Wq, Wk, 0, 0, tid, q0, q1, k0v, k1v);
        storeW(smem, W_BASE, tid, q0, q1, k0v, k1v);
    }
    cp_wait_all();
    __syncthreads();

    const float scale = 0.14433756729740643f;  // 48^-0.5
    const int wm0 = wid * 16;
    const int a_row = wm0 + (lane & 15);
    const int a_cadd = ((lane >> 4) << 3);
    const int b_radd = ((lane >> 4) & 1) * 8 + (lane & 7);
    const int b_cadd = ((lane >> 3) & 1) * 8;

    float accQ[6][4], accK[6][4];
    int h = 0, kc = 0;
    for (int it = 0; it < 96; ++it) {
        const int buf = it & 1;
        const uint32_t aB = sb + buf * A_BUF;
        const uint32_t wB = sb + W_BASE + buf * W_BUF;
        const int nit = it + 1;
        const int nbuf = nit & 1;
        int nh = h, nkc = kc + 1;
        if (nkc == 12) {
            nkc = 0;
            nh = h + 1;
        }

        if (kc == 0) {
#pragma unroll
            for (int i = 0; i < 6; ++i)
#pragma unroll
                for (int j = 0; j < 4; ++j) {
                    accQ[i][j] = 0.f;
                    accK[i][j] = 0.f;
                }
        }

        // issue next-iteration loads (cp.async for A, LDG-to-regs for W) BEFORE MMA
        float pq0[3], pq1[3], pk0[3], pk1[3];
        if (nit < 96) {
            stage_A(sb + nbuf * A_BUF, m0, nbr, tot, r, nkc * KC, tid);
            loadW(Wq, Wk, nh * DHH, nkc * KC, tid, pq0, pq1, pk0, pk1);
        }

        // ---- MMA on current buffer ----
#pragma unroll
        for (int ks = 0; ks < 2; ++ks) {
            const uint32_t aoff = aB + a_row * ASTRIDE + (ks * 16 + a_cadd) * 2;
            uint32_t qh0, qh1, qh2, qh3;
            uint32_t kh0, kh1, kh2, kh3;
            ldsm4(aoff + AQH, qh0, qh1, qh2, qh3);
            ldsm4(aoff + AKH, kh0, kh1, kh2, kh3);
#pragma unroll
            for (int ntp = 0; ntp < 3; ++ntp) {
                const uint32_t boff = wB + (ntp * 16 + b_radd) * ASTRIDE + (ks * 16 + b_cadd) * 2;
                uint32_t wq0, wq1, wq2, wq3;
                uint32_t vk0, vk1, vk2, vk3;
                ldsm4(boff + WQH, wq0, wq1, wq2, wq3);
                ldsm4(boff + WKH, vk0, vk1, vk2, vk3);
                mma_f16(accQ[2 * ntp], qh0, qh1, qh2, qh3, wq0, wq1);
                mma_f16(accQ[2 * ntp + 1], qh0, qh1, qh2, qh3, wq2, wq3);
                mma_f16(accK[2 * ntp], kh0, kh1, kh2, kh3, vk0, vk1);
                mma_f16(accK[2 * ntp + 1], kh0, kh1, kh2, kh3, vk2, vk3);
            }
        }

        // ---- epilogue at end of head: diagonal pairing + row sums ----
        if (kc == 11) {
            float sl = 0.f, sh2 = 0.f;
#pragma unroll
            for (int nt = 0; nt < 6; ++nt) {
                sl += accQ[nt][0] * accK[nt][0] + accQ[nt][1] * accK[nt][1];
                sh2 += accQ[nt][2] * accK[nt][2] + accQ[nt][3] * accK[nt][3];
            }
            sl += __shfl_xor_sync(0xffffffffu, sl, 1);
            sl += __shfl_xor_sync(0xffffffffu, sl, 2);
            sh2 += __shfl_xor_sync(0xffffffffu, sh2, 1);
            sh2 += __shfl_xor_sync(0xffffffffu, sh2, 2);
            if ((lane & 3) == 0) {
                const int ur = m0 + wm0 + (lane >> 2);
#pragma unroll
                for (int half = 0; half < 2; ++half) {
                    const int u = ur + half * 8;
                    const float s = half ? sh2 : sl;
                    if (u < tot) {
                        const int b = (u >= nbr);
                        const int t = u - b * nbr;
                        const int ig = r + t;
                        g_dots[(((size_t)b * HH + h) * LL + ig) * LL + t] = s * scale;
                    }
                }
            }
        }

        // convert + store prefetched W into next buffer (after MMA; LDG latency was hidden)
        if (nit < 96) {
            storeW(smem, W_BASE + nbuf * W_BUF, tid, pq0, pq1, pk0, pk1);
        }

        cp_wait_all();
        __syncthreads();
        h = nh;
        kc = nkc;
    }
}

// ======================= causal softmax =======================
__global__ void __launch_bounds__(128) softmax_kernel() {
    const int row = blockIdx.x * 4 + (threadIdx.x >> 5);
    if (row >= BB * HH * LL) return;
    const int lane = threadIdx.x & 31;
    const int i = row % LL;
    float* d = g_dots + (size_t)row * LL;
    const int n = i + 1;
    float mx = -1e30f;
    for (int j = lane; j < n; j += 32) mx = fmaxf(mx, d[j]);
    for (int o = 16; o; o >>= 1) mx = fmaxf(mx, __shfl_xor_sync(0xffffffffu, mx, o));
    float s = 0.f;
    for (int j = lane; j < n; j += 32) {
        float e = __expf(d[j] - mx);
        d[j] = e;
        s += e;
    }
    for (int o = 16; o; o >>= 1) s += __shfl_xor_sync(0xffffffffu, s, o);
    const float inv = 1.f / s;
    for (int j = lane; j < n; j += 32) d[j] *= inv;
}

// ======================= attn @ v =======================
__global__ void __launch_bounds__(192) av_kernel() {
    const int local = threadIdx.x / DHH;
    const int dd = threadIdx.x % DHH;
    const int task = blockIdx.x * 4 + local;
    if (task >= BB * HH * LL) return;
    const int i = task % LL;
    const int bh = task / LL;
    const int h = bh % HH;
    const int b = bh / HH;
    const float* attn = g_dots + (size_t)task * LL;
    const float* vp = g_v + (size_t)b * LL * NN + h * DHH + dd;
    float acc = 0.f;
    for (int j = 0; j <= i; ++j) acc += attn[j] * vp[(size_t)j * NN];
    g_ao[((size_t)b * LL + i) * NN + h * DHH + dd] = acc;
}

// ======================= launcher =======================
extern "C" void kernel_launch(void* const* d_in, const int* in_sizes, int n_in,
                              void* d_out, int out_size) {
    const float* x = (const float*)d_in[0];
    const float* gamma = (const float*)d_in[1];
    const float* beta = (const float*)d_in[2];
    const float* uq = (const float*)d_in[3];
    const float* uk = (const float*)d_in[4];
    const float* wv = (const float*)d_in[5];
    const float* wo = (const float*)d_in[6];
    const float* bo = (const float*)d_in[7];
    float* out = (float*)d_out;

    float* g_xn_p;
    float* g_v_p;
    float* g_ao_p;
    cudaGetSymbolAddress((void**)&g_xn_p, g_xn);
    cudaGetSymbolAddress((void**)&g_v_p, g_v);
    cudaGetSymbolAddress((void**)&g_ao_p, g_ao);
    cudaFuncSetAttribute(dots_mma_kernel, cudaFuncAttributeMaxDynamicSharedMemorySize, SM_TOTAL);

    ln_kernel<<<BB * LL, 128>>>(x, gamma, beta);
    gemm32_kernel<<<dim3(12, 12), 128>>>(g_xn_p, wv, nullptr, g_v_p, 0);
    dots_mma_kernel<<<dim3(3, LL), 256, SM_TOTAL>>>(uq, uk);
    softmax_kernel<<<(BB * HH * LL + 3) / 4, 128>>>();
    av_kernel<<<(BB * HH * LL + 3) / 4, 192>>>();
    gemm32_kernel<<<dim3(12, 12), 128>>>(g_ao_p, wo, bo, out, 1);
}

// round 15
// speedup vs baseline: 1.0068x; 1.0068x over previous
#include <cuda_runtime.h>
#include <cuda_fp16.h>
#include <stdint.h>
#include <math.h>

#define BB 2
#define LL 192
#define DD 384
#define HH 8
#define DHH 48
#define NN 384
#define EPSF 1e-5f

// Scratch (allocation-free rule: __device__ globals)
__device__ float g_xn[BB * LL * DD];   // layernormed x (fp32, for v-proj)
__device__ __half g_xh[BB * LL * DD];  // xn fp16
__device__ float g_v[BB * LL * NN];    // v projection
__device__ float g_dots[BB * HH * LL * LL];  // attention logits -> probs (in place)
__device__ float g_ao[BB * LL * NN];         // attn @ v, head-merged

// ======================= baseline-PTX tensor helpers (sm_80+) =======================
__device__ __forceinline__ uint32_t smem_u32(const void* p) {
    uint32_t a;
    asm("{ .reg .u64 t; cvta.to.shared.u64 t, %1; cvt.u32.u64 %0, t; }" : "=r"(a) : "l"(p));
    return a;
}
__device__ __forceinline__ void ldsm4(uint32_t addr, uint32_t& r0, uint32_t& r1, uint32_t& r2,
                                      uint32_t& r3) {
    asm volatile("ldmatrix.sync.aligned.m8n8.x4.shared.b16 {%0,%1,%2,%3}, [%4];"
                 : "=r"(r0), "=r"(r1), "=r"(r2), "=r"(r3)
                 : "r"(addr));
}
__device__ __forceinline__ void mma_f16(float* c, uint32_t a0, uint32_t a1, uint32_t a2,
                                        uint32_t a3, uint32_t b0, uint32_t b1) {
    asm volatile(
        "mma.sync.aligned.m16n8k16.row.col.f32.f16.f16.f32 "
        "{%0,%1,%2,%3}, {%4,%5,%6,%7}, {%8,%9}, {%0,%1,%2,%3};"
        : "+f"(c[0]), "+f"(c[1]), "+f"(c[2]), "+f"(c[3])
        : "r"(a0), "r"(a1), "r"(a2), "r"(a3), "r"(b0), "r"(b1));
}
__device__ __forceinline__ void cp16(uint32_t dst, const void* src, int src_bytes) {
    asm volatile("cp.async.cg.shared.global [%0], [%1], 16, %2;" ::"r"(dst), "l"(src),
                 "r"(src_bytes)
                 : "memory");
}
__device__ __forceinline__ void cp_wait_all() {
    asm volatile("cp.async.wait_all;" ::: "memory");
}

// ======================= LayerNorm (+ fp16 precompute) =======================
__global__ void __launch_bounds__(128) ln_kernel(const float* __restrict__ x,
                                                 const float* __restrict__ gamma,
                                                 const float* __restrict__ beta) {
    const int row = blockIdx.x;
    const int tid = threadIdx.x;
    const float* xr = x + (size_t)row * DD;
    float s = 0.f, s2 = 0.f;
    for (int c = tid; c < DD; c += 128) {
        float t = xr[c];
        s += t;
        s2 += t * t;
    }
    for (int o = 16; o; o >>= 1) {
        s += __shfl_xor_sync(0xffffffffu, s, o);
        s2 += __shfl_xor_sync(0xffffffffu, s2, o);
    }
    __shared__ float sh[8];
    const int w = tid >> 5;
    if ((tid & 31) == 0) {
        sh[w] = s;
        sh[4 + w] = s2;
    }
    __syncthreads();
    s = sh[0] + sh[1] + sh[2] + sh[3];
    s2 = sh[4] + sh[5] + sh[6] + sh[7];
    const float mu = s * (1.0f / DD);
    const float var = s2 * (1.0f / DD) - mu * mu;
    const float rstd = rsqrtf(var + EPSF);
    for (int c = tid; c < DD; c += 128) {
        const float v = (xr[c] - mu) * rstd * gamma[c] + beta[c];
        g_xn[(size_t)row * DD + c] = v;
        g_xh[(size_t)row * DD + c] = __float2half_rn(v);
    }
}

// ======================= small fp32 GEMM, 32x32 tiles (v / o projections) =======================
__global__ void __launch_bounds__(128) gemm32_kernel(const float* __restrict__ A,
                                                     const float* __restrict__ Bw,
                                                     const float* __restrict__ bias,
                                                     float* __restrict__ C, int has_bias) {
    __shared__ float As[32][33];
    __shared__ float Bs[32][36];
    const int bm = blockIdx.y * 32, bn = blockIdx.x * 32;
    const int tid = threadIdx.x;
    const int tx = tid & 7, ty = tid >> 3;  // 8 x 4 cols, 16 x 2 rows
    float acc[2][4] = {};
    for (int k0 = 0; k0 < 384; k0 += 32) {
#pragma unroll
        for (int idx = tid; idx < 1024; idx += 128) {
            const int m = idx >> 5, kk = idx & 31;
            As[kk][m] = A[(size_t)(bm + m) * 384 + k0 + kk];
        }
#pragma unroll
        for (int idx = tid; idx < 1024; idx += 128) {
            const int kk = idx >> 5, n = idx & 31;
            Bs[kk][n] = Bw[(size_t)(k0 + kk) * 384 + bn + n];
        }
        __syncthreads();
#pragma unroll
        for (int kk = 0; kk < 32; ++kk) {
            const float a0 = As[kk][ty * 2], a1 = As[kk][ty * 2 + 1];
            const float4 b4 = *(const float4*)&Bs[kk][tx * 4];
            const float b[4] = {b4.x, b4.y, b4.z, b4.w};
#pragma unroll
            for (int j = 0; j < 4; ++j) {
                acc[0][j] += a0 * b[j];
                acc[1][j] += a1 * b[j];
            }
        }
        __syncthreads();
    }
#pragma unroll
    for (int i = 0; i < 2; ++i)
#pragma unroll
        for (int j = 0; j < 4; ++j) {
            const int row = bm + ty * 2 + i, col = bn + tx * 4 + j;
            float o = acc[i][j];
            if (has_bias) o += bias[col];
            C[(size_t)row * 384 + col] = o;
        }
}

// ======================= dots via mma.sync HMMA (fp16 x fp16, distance-2 W prefetch) ======
// CTA = (r = blockIdx.y, 128-row tile = blockIdx.x). Logical row u in [0, 2*(L-r)):
// b = u>=L-r, t = u-b*(L-r). Q row = xn[b,r+t] @ u_q[L-1-r], K row = xn[b,t] @ u_k[r].
// W[it+2] is LDG'd into a ping-pong register set at iteration it and stored to smem at
// the end of it (W[it+1] stored then) -> ~2 iterations of DRAM-latency cover.
#define MT 128
#define KC 32
#define ASTRIDE 80   // 64B row + 16B pad: 16B-aligned stride, conflict-free ldmatrix
#define A_ARR 10240  // 128*80
#define A_BUF 20480  // 2 arrays (QH, KH)
#define W_ARR 3840   // 48*80
#define W_BUF 7680   // 2 arrays (WQH, WKH)
#define W_BASE 40960  // 2*A_BUF
#define SM_TOTAL (W_BASE + 2 * W_BUF)  // 56320 bytes

#define AQH 0
#define AKH 10240
#define WQH 0
#define WKH 3840

__device__ __forceinline__ void stage_A(uint32_t abase, int m0, int nbr, int tot, int r, int k0,
                                        int tid) {
    const char* xh = (const char*)g_xh;
#pragma unroll
    for (int q = tid; q < 512; q += 256) {
        const int m = q >> 2, seg = q & 3;
        const int u = m0 + m;
        const int valid = (u < tot) ? 16 : 0;
        int b = (u >= nbr) ? 1 : 0;
        int t = u - b * nbr;
        if (!valid) {
            b = 0;
            t = 0;
        }
        const int rowq = b * LL + r + t;
        const int rowk = b * LL + t;
        const size_t boff = (size_t)k0 * 2 + seg * 16;
        const uint32_t so = abase + m * ASTRIDE + seg * 16;
        cp16(so + AQH, xh + (size_t)rowq * (DD * 2) + boff, valid);
        cp16(so + AKH, xh + (size_t)rowk * (DD * 2) + boff, valid);
    }
}

// W prefetch: 3 tasks/thread, each task = (n, k2) pair; loads 2 consecutive-k fp32 for Q and K.
__device__ __forceinline__ void loadW(const float* __restrict__ Wq, const float* __restrict__ Wk,
                                      int n0, int k0, int tid, float* wq0, float* wq1, float* wk0,
                                      float* wk1) {
#pragma unroll
    for (int s = 0; s < 3; ++s) {
        const int idx = tid + s * 256;  // < 768
        const int k2 = idx / 48;
        const int n = idx - k2 * 48;
        const size_t g0 = (size_t)(k0 + 2 * k2) * NN + n0 + n;
        wq0[s] = Wq[g0];
        wq1[s] = Wq[g0 + NN];
        wk0[s] = Wk[g0];
        wk1[s] = Wk[g0 + NN];
    }
}

__device__ __forceinline__ void storeW(char* smem, uint32_t wrel, int tid, const float* wq0,
                                       const float* wq1, const float* wk0, const float* wk1) {
#pragma unroll
    for (int s = 0; s < 3; ++s) {
        const int idx = tid + s * 256;
        const int k2 = idx / 48;
        const int n = idx - k2 * 48;
        __half2 qh, kh;
        qh.x = __float2half_rn(wq0[s]);
        qh.y = __float2half_rn(wq1[s]);
        kh.x = __float2half_rn(wk0[s]);
        kh.y = __float2half_rn(wk1[s]);
        const uint32_t so = wrel + n * ASTRIDE + k2 * 4;
        *(uint32_t*)(smem + so + WQH) = *(uint32_t*)&qh;
        *(uint32_t*)(smem + so + WKH) = *(uint32_t*)&kh;
    }
}

__global__ void __launch_bounds__(256, 2) dots_mma_kernel(const float* __restrict__ uq,
                                                          const float* __restrict__ uk) {
    const int r = blockIdx.y;
    const int m0 = blockIdx.x * MT;
    const int nbr = LL - r;
    const int tot = 2 * nbr;
    if (m0 >= tot) return;

    extern __shared__ char smem[];
    const uint32_t sb = smem_u32(smem);
    const int tid = threadIdx.x;
    const int wid = tid >> 5, lane = tid & 31;

    const float* __restrict__ Wq = uq + (size_t)(LL - 1 - r) * DD * NN;
    const float* __restrict__ Wk = uk + (size_t)r * DD * NN;

    // W register ping-pong sets. Even it: store B(=W[it+1]), load A(=W[it+2]).
    //                             Odd it:  store A,            load B.
    float aq0[3], aq1[3], ak0[3], ak1[3];  // set A
    float bq0[3], bq1[3], bk0[3], bk1[3];  // set B

    // prologue: A[0] staged; W[0] loaded+stored; W[1] loaded into set B (in flight)
    stage_A(sb, m0, nbr, tot, r, 0, tid);
    loadW(Wq, Wk, 0, 0, tid, aq0, aq1, ak0, ak1);
    storeW(smem, W_BASE, tid, aq0, aq1, ak0, ak1);  // W[0] -> slot 0
    loadW(Wq, Wk, 0, KC, tid, bq0, bq1, bk0, bk1);  // W[1] (h=0, kc=1)
    cp_wait_all();
    __syncthreads();

    const float scale = 0.14433756729740643f;  // 48^-0.5
    const int wm0 = wid * 16;
    const int a_row = wm0 + (lane & 15);
    const int a_cadd = ((lane >> 4) << 3);
    const int b_radd = ((lane >> 4) & 1) * 8 + (lane & 7);
    const int b_cadd = ((lane >> 3) & 1) * 8;

    float accQ[6][4], accK[6][4];
    int h = 0, kc = 0;

#define DOTS_BODY(IT, Lq0, Lq1, Lk0, Lk1, Sq0, Sq1, Sk0, Sk1)                                     \
    {                                                                                             \
        const int buf = (IT) & 1;                                                                 \
        const uint32_t aB = sb + buf * A_BUF;                                                     \
        const uint32_t wB = sb + W_BASE + buf * W_BUF;                                            \
        int nh1 = h, nkc1 = kc + 1;                                                               \
        if (nkc1 == 12) { nkc1 = 0; nh1 = h + 1; }                                                \
        int nh2 = nh1, nkc2 = nkc1 + 1;                                                           \
        if (nkc2 == 12) { nkc2 = 0; nh2 = nh1 + 1; }                                              \
        if (kc == 0) {                                                                            \
            _Pragma("unroll") for (int i = 0; i < 6; ++i) _Pragma("unroll")                       \
                for (int j = 0; j < 4; ++j) {                                                     \
                accQ[i][j] = 0.f;                                                                 \
                accK[i][j] = 0.f;                                                                 \
            }                                                                                     \
        }                                                                                         \
        if ((IT) + 1 < 96) stage_A(sb + (((IT) + 1) & 1) * A_BUF, m0, nbr, tot, r, nkc1 * KC, tid);\
        if ((IT) + 2 < 96) loadW(Wq, Wk, nh2 * DHH, nkc2 * KC, tid, Lq0, Lq1, Lk0, Lk1);          \
        _Pragma("unroll") for (int ks = 0; ks < 2; ++ks) {                                        \
            const uint32_t aoff = aB + a_row * ASTRIDE + (ks * 16 + a_cadd) * 2;                  \
            uint32_t qh0, qh1, qh2, qh3, kh0, kh1, kh2, kh3;                                      \
            ldsm4(aoff + AQH, qh0, qh1, qh2, qh3);                                                \
            ldsm4(aoff + AKH, kh0, kh1, kh2, kh3);                                                \
            _Pragma("unroll") for (int ntp = 0; ntp < 3; ++ntp) {                                 \
                const uint32_t boff =                                                             \
                    wB + (ntp * 16 + b_radd) * ASTRIDE + (ks * 16 + b_cadd) * 2;                  \
                uint32_t wq0, wq1, wq2, wq3, vk0, vk1, vk2, vk3;                                  \
                ldsm4(boff + WQH, wq0, wq1, wq2, wq3);                                            \
                ldsm4(boff + WKH, vk0, vk1, vk2, vk3);                                            \
                mma_f16(accQ[2 * ntp], qh0, qh1, qh2, qh3, wq0, wq1);                             \
                mma_f16(accQ[2 * ntp + 1], qh0, qh1, qh2, qh3, wq2, wq3);                         \
                mma_f16(accK[2 * ntp], kh0, kh1, kh2, kh3, vk0, vk1);                             \
                mma_f16(accK[2 * ntp + 1], kh0, kh1, kh2, kh3, vk2, vk3);                         \
            }                                                                                     \
        }                                                                                         \
        if (kc == 11) {                                                                           \
            float sl = 0.f, sh2 = 0.f;                                                            \
            _Pragma("unroll") for (int nt = 0; nt < 6; ++nt) {                                    \
                sl += accQ[nt][0] * accK[nt][0] + accQ[nt][1] * accK[nt][1];                      \
                sh2 += accQ[nt][2] * accK[nt][2] + accQ[nt][3] * accK[nt][3];                     \
            }                                                                                     \
            sl += __shfl_xor_sync(0xffffffffu, sl, 1);                                            \
            sl += __shfl_xor_sync(0xffffffffu, sl, 2);                                            \
            sh2 += __shfl_xor_sync(0xffffffffu, sh2, 1);                                          \
            sh2 += __shfl_xor_sync(0xffffffffu, sh2, 2);                                          \
            if ((lane & 3) == 0) {                                                                \
                const int ur = m0 + wm0 + (lane >> 2);                                            \
                _Pragma("unroll") for (int half = 0; half < 2; ++half) {                          \
                    const int u = ur + half * 8;                                                  \
                    const float s = half ? sh2 : sl;                                              \
                    if (u < tot) {                                                                \
                        const int b = (u >= nbr);                                                 \
                        const int t = u - b * nbr;                                                \
                        const int ig = r + t;                                                     \
                        g_dots[(((size_t)b * HH + h) * LL + ig) * LL + t] = s * scale;            \
                    }                                                                             \
                }                                                                                 \
            }                                                                                     \
        }                                                                                         \
        if ((IT) + 1 < 96)                                                                        \
            storeW(smem, W_BASE + (((IT) + 1) & 1) * W_BUF, tid, Sq0, Sq1, Sk0, Sk1);             \
        cp_wait_all();                                                                            \
        __syncthreads();                                                                          \
        h = nh1;                                                                                  \
        kc = nkc1;                                                                                \
    }

    for (int itp = 0; itp < 48; ++itp) {
        const int it0 = 2 * itp;
        // even: load into set A (W[it+2]), store set B (W[it+1])
        DOTS_BODY(it0, aq0, aq1, ak0, ak1, bq0, bq1, bk0, bk1);
        // odd: load into set B, store set A
        DOTS_BODY(it0 + 1, bq0, bq1, bk0, bk1, aq0, aq1, ak0, ak1);
    }
#undef DOTS_BODY
}

// ======================= causal softmax =======================
__global__ void __launch_bounds__(128) softmax_kernel() {
    const int row = blockIdx.x * 4 + (threadIdx.x >> 5);
    if (row >= BB * HH * LL) return;
    const int lane = threadIdx.x & 31;
    const int i = row % LL;
    float* d = g_dots + (size_t)row * LL;
    const int n = i + 1;
    float mx = -1e30f;
    for (int j = lane; j < n; j += 32) mx = fmaxf(mx, d[j]);
    for (int o = 16; o; o >>= 1) mx = fmaxf(mx, __shfl_xor_sync(0xffffffffu, mx, o));
    float s = 0.f;
    for (int j = lane; j < n; j += 32) {
        float e = __expf(d[j] - mx);
        d[j] = e;
        s += e;
    }
    for (int o = 16; o; o >>= 1) s += __shfl_xor_sync(0xffffffffu, s, o);
    const float inv = 1.f / s;
    for (int j = lane; j < n; j += 32) d[j] *= inv;
}

// ======================= attn @ v =======================
__global__ void __launch_bounds__(192) av_kernel() {
    const int local = threadIdx.x / DHH;
    const int dd = threadIdx.x % DHH;
    const int task = blockIdx.x * 4 + local;
    if (task >= BB * HH * LL) return;
    const int i = task % LL;
    const int bh = task / LL;
    const int h = bh % HH;
    const int b = bh / HH;
    const float* attn = g_dots + (size_t)task * LL;
    const float* vp = g_v + (size_t)b * LL * NN + h * DHH + dd;
    float acc = 0.f;
    for (int j = 0; j <= i; ++j) acc += attn[j] * vp[(size_t)j * NN];
    g_ao[((size_t)b * LL + i) * NN + h * DHH + dd] = acc;
}

// ======================= launcher =======================
extern "C" void kernel_launch(void* const* d_in, const int* in_sizes, int n_in,
                              void* d_out, int out_size) {
    const float* x = (const float*)d_in[0];
    const float* gamma = (const float*)d_in[1];
    const float* beta = (const float*)d_in[2];
    const float* uq = (const float*)d_in[3];
    const float* uk = (const float*)d_in[4];
    const float* wv = (const float*)d_in[5];
    const float* wo = (const float*)d_in[6];
    const float* bo = (const float*)d_in[7];
    float* out = (float*)d_out;

    float* g_xn_p;
    float* g_v_p;
    float* g_ao_p;
    cudaGetSymbolAddress((void**)&g_xn_p, g_xn);
    cudaGetSymbolAddress((void**)&g_v_p, g_v);
    cudaGetSymbolAddress((void**)&g_ao_p, g_ao);
    cudaFuncSetAttribute(dots_mma_kernel, cudaFuncAttributeMaxDynamicSharedMemorySize, SM_TOTAL);

    ln_kernel<<<BB * LL, 128>>>(x, gamma, beta);
    gemm32_kernel<<<dim3(12, 12), 128>>>(g_xn_p, wv, nullptr, g_v_p, 0);
    dots_mma_kernel<<<dim3(3, LL), 256, SM_TOTAL>>>(uq, uk);
    softmax_kernel<<<(BB * HH * LL + 3) / 4, 128>>>();
    av_kernel<<<(BB * HH * LL + 3) / 4, 192>>>();
    gemm32_kernel<<<dim3(12, 12), 128>>>(g_ao_p, wo, bo, out, 1);
}

// round 16
// speedup vs baseline: 1.3532x; 1.3440x over previous
#include <cuda_runtime.h>
#include <cuda_fp16.h>
#include <stdint.h>
#include <math.h>

#define BB 2
#define LL 192
#define DD 384
#define HH 8
#define DHH 48
#define NN 384
#define EPSF 1e-5f

// Scratch (allocation-free rule: __device__ globals)
__device__ float g_xn[BB * LL * DD];   // layernormed x (fp32, for v-proj)
__device__ __half g_xh[BB * LL * DD];  // xn fp16
__device__ float g_v[BB * LL * NN];    // v projection
__device__ float g_dots[BB * HH * LL * LL];  // attention logits -> probs (in place)
__device__ float g_ao[BB * LL * NN];         // attn @ v, head-merged

// ======================= baseline-PTX tensor helpers (sm_80+) =======================
__device__ __forceinline__ uint32_t smem_u32(const void* p) {
    uint32_t a;
    asm("{ .reg .u64 t; cvta.to.shared.u64 t, %1; cvt.u32.u64 %0, t; }" : "=r"(a) : "l"(p));
    return a;
}
__device__ __forceinline__ void ldsm4(uint32_t addr, uint32_t& r0, uint32_t& r1, uint32_t& r2,
                                      uint32_t& r3) {
    asm volatile("ldmatrix.sync.aligned.m8n8.x4.shared.b16 {%0,%1,%2,%3}, [%4];"
                 : "=r"(r0), "=r"(r1), "=r"(r2), "=r"(r3)
                 : "r"(addr));
}
__device__ __forceinline__ void mma_f16(float* c, uint32_t a0, uint32_t a1, uint32_t a2,
                                        uint32_t a3, uint32_t b0, uint32_t b1) {
    asm volatile(
        "mma.sync.aligned.m16n8k16.row.col.f32.f16.f16.f32 "
        "{%0,%1,%2,%3}, {%4,%5,%6,%7}, {%8,%9}, {%0,%1,%2,%3};"
        : "+f"(c[0]), "+f"(c[1]), "+f"(c[2]), "+f"(c[3])
        : "r"(a0), "r"(a1), "r"(a2), "r"(a3), "r"(b0), "r"(b1));
}
__device__ __forceinline__ void cp16(uint32_t dst, const void* src, int src_bytes) {
    asm volatile("cp.async.cg.shared.global [%0], [%1], 16, %2;" ::"r"(dst), "l"(src),
                 "r"(src_bytes)
                 : "memory");
}
__device__ __forceinline__ void cp_wait_all() {
    asm volatile("cp.async.wait_all;" ::: "memory");
}

// ======================= LayerNorm (+ fp16 precompute) =======================
__global__ void __launch_bounds__(128) ln_kernel(const float* __restrict__ x,
                                                 const float* __restrict__ gamma,
                                                 const float* __restrict__ beta) {
    const int row = blockIdx.x;
    const int tid = threadIdx.x;
    const float* xr = x + (size_t)row * DD;
    float s = 0.f, s2 = 0.f;
    for (int c = tid; c < DD; c += 128) {
        float t = xr[c];
        s += t;
        s2 += t * t;
    }
    for (int o = 16; o; o >>= 1) {
        s += __shfl_xor_sync(0xffffffffu, s, o);
        s2 += __shfl_xor_sync(0xffffffffu, s2, o);
    }
    __shared__ float sh[8];
    const int w = tid >> 5;
    if ((tid & 31) == 0) {
        sh[w] = s;
        sh[4 + w] = s2;
    }
    __syncthreads();
    s = sh[0] + sh[1] + sh[2] + sh[3];
    s2 = sh[4] + sh[5] + sh[6] + sh[7];
    const float mu = s * (1.0f / DD);
    const float var = s2 * (1.0f / DD) - mu * mu;
    const float rstd = rsqrtf(var + EPSF);
    for (int c = tid; c < DD; c += 128) {
        const float v = (xr[c] - mu) * rstd * gamma[c] + beta[c];
        g_xn[(size_t)row * DD + c] = v;
        g_xh[(size_t)row * DD + c] = __float2half_rn(v);
    }
}

// ======================= small fp32 GEMM, 32x32 tiles (v / o projections) =======================
__global__ void __launch_bounds__(128) gemm32_kernel(const float* __restrict__ A,
                                                     const float* __restrict__ Bw,
                                                     const float* __restrict__ bias,
                                                     float* __restrict__ C, int has_bias) {
    __shared__ float As[32][33];
    __shared__ float Bs[32][36];
    const int bm = blockIdx.y * 32, bn = blockIdx.x * 32;
    const int tid = threadIdx.x;
    const int tx = tid & 7, ty = tid >> 3;  // 8 x 4 cols, 16 x 2 rows
    float acc[2][4] = {};
    for (int k0 = 0; k0 < 384; k0 += 32) {
#pragma unroll
        for (int idx = tid; idx < 1024; idx += 128) {
            const int m = idx >> 5, kk = idx & 31;
            As[kk][m] = A[(size_t)(bm + m) * 384 + k0 + kk];
        }
#pragma unroll
        for (int idx = tid; idx < 1024; idx += 128) {
            const int kk = idx >> 5, n = idx & 31;
            Bs[kk][n] = Bw[(size_t)(k0 + kk) * 384 + bn + n];
        }
        __syncthreads();
#pragma unroll
        for (int kk = 0; kk < 32; ++kk) {
            const float a0 = As[kk][ty * 2], a1 = As[kk][ty * 2 + 1];
            const float4 b4 = *(const float4*)&Bs[kk][tx * 4];
            const float b[4] = {b4.x, b4.y, b4.z, b4.w};
#pragma unroll
            for (int j = 0; j < 4; ++j) {
                acc[0][j] += a0 * b[j];
                acc[1][j] += a1 * b[j];
            }
        }
        __syncthreads();
    }
#pragma unroll
    for (int i = 0; i < 2; ++i)
#pragma unroll
        for (int j = 0; j < 4; ++j) {
            const int row = bm + ty * 2 + i, col = bn + tx * 4 + j;
            float o = acc[i][j];
            if (has_bias) o += bias[col];
            C[(size_t)row * 384 + col] = o;
        }
}

// ======================= dots via mma.sync HMMA (fp16 x fp16, KC=64) ==========
// CTA = (r = blockIdx.y, 128-row tile = blockIdx.x). Logical row u in [0, 2*(L-r)):
// b = u>=L-r, t = u-b*(L-r). Q row = xn[b,r+t] @ u_q[L-1-r], K row = xn[b,t] @ u_k[r].
// KC=64: 48 iterations x 48 MMAs -> per-iteration fixed cost (barriers, cp waits,
// staging issue) halved vs KC=32 while keeping R13-level latency cover per iteration.
#define MT 128
#define KC 64
#define ASTRIDE 144  // 128B row + 16B pad: 16B-aligned, conflict-free ldmatrix
#define A_ARR 18432  // 128*144
#define A_BUF 36864  // 2 arrays (QH, KH)
#define W_ARR 6912   // 48*144
#define W_BUF 13824  // 2 arrays (WQH, WKH)
#define W_BASE 73728  // 2*A_BUF
#define SM_TOTAL (W_BASE + 2 * W_BUF)  // 101376 bytes

#define AQH 0
#define AKH 18432
#define WQH 0
#define WKH 6912

__device__ __forceinline__ void stage_A(uint32_t abase, int m0, int nbr, int tot, int r, int k0,
                                        int tid) {
    const char* xh = (const char*)g_xh;
#pragma unroll
    for (int q = tid; q < 1024; q += 256) {
        const int m = q >> 3, seg = q & 7;
        const int u = m0 + m;
        const int valid = (u < tot) ? 16 : 0;
        int b = (u >= nbr) ? 1 : 0;
        int t = u - b * nbr;
        if (!valid) {
            b = 0;
            t = 0;
        }
        const int rowq = b * LL + r + t;
        const int rowk = b * LL + t;
        const size_t boff = (size_t)k0 * 2 + seg * 16;
        const uint32_t so = abase + m * ASTRIDE + seg * 16;
        cp16(so + AQH, xh + (size_t)rowq * (DD * 2) + boff, valid);
        cp16(so + AKH, xh + (size_t)rowk * (DD * 2) + boff, valid);
    }
}

// W prefetch: 6 tasks/thread, each task = (n, k2) pair; loads 2 consecutive-k fp32 for Q and K.
__device__ __forceinline__ void loadW(const float* __restrict__ Wq, const float* __restrict__ Wk,
                                      int n0, int k0, int tid, float* wq0, float* wq1, float* wk0,
                                      float* wk1) {
#pragma unroll
    for (int s = 0; s < 6; ++s) {
        const int idx = tid + s * 256;  // < 1536
        const int k2 = idx / 48;        // 0..31
        const int n = idx - k2 * 48;
        const size_t g0 = (size_t)(k0 + 2 * k2) * NN + n0 + n;
        wq0[s] = Wq[g0];
        wq1[s] = Wq[g0 + NN];
        wk0[s] = Wk[g0];
        wk1[s] = Wk[g0 + NN];
    }
}

__device__ __forceinline__ void storeW(char* smem, uint32_t wrel, int tid, const float* wq0,
                                       const float* wq1, const float* wk0, const float* wk1) {
#pragma unroll
    for (int s = 0; s < 6; ++s) {
        const int idx = tid + s * 256;
        const int k2 = idx / 48;
        const int n = idx - k2 * 48;
        __half2 qh, kh;
        qh.x = __float2half_rn(wq0[s]);
        qh.y = __float2half_rn(wq1[s]);
        kh.x = __float2half_rn(wk0[s]);
        kh.y = __float2half_rn(wk1[s]);
        const uint32_t so = wrel + n * ASTRIDE + k2 * 4;
        *(uint32_t*)(smem + so + WQH) = *(uint32_t*)&qh;
        *(uint32_t*)(smem + so + WKH) = *(uint32_t*)&kh;
    }
}

__global__ void __launch_bounds__(256, 2) dots_mma_kernel(const float* __restrict__ uq,
                                                          const float* __restrict__ uk) {
    const int r = blockIdx.y;
    const int m0 = blockIdx.x * MT;
    const int nbr = LL - r;
    const int tot = 2 * nbr;
    if (m0 >= tot) return;

    extern __shared__ char smem[];
    const uint32_t sb = smem_u32(smem);
    const int tid = threadIdx.x;
    const int wid = tid >> 5, lane = tid & 31;

    const float* __restrict__ Wq = uq + (size_t)(LL - 1 - r) * DD * NN;
    const float* __restrict__ Wk = uk + (size_t)r * DD * NN;

    // prologue: stage it=0 into buffer 0
    stage_A(sb, m0, nbr, tot, r, 0, tid);
    {
        float q0[6], q1[6], k0v[6], k1v[6];
        loadW(Wq, Wk, 0, 0, tid, q0, q1, k0v, k1v);
        storeW(smem, W_BASE, tid, q0, q1, k0v, k1v);
    }
    cp_wait_all();
    __syncthreads();

    const float scale = 0.14433756729740643f;  // 48^-0.5
    const int wm0 = wid * 16;
    const int a_row = wm0 + (lane & 15);
    const int a_cadd = ((lane >> 4) << 3);
    const int b_radd = ((lane >> 4) & 1) * 8 + (lane & 7);
    const int b_cadd = ((lane >> 3) & 1) * 8;

    float accQ[6][4], accK[6][4];
    int h = 0, kc = 0;
    for (int it = 0; it < 48; ++it) {
        const int buf = it & 1;
        const uint32_t aB = sb + buf * A_BUF;
        const uint32_t wB = sb + W_BASE + buf * W_BUF;
        const int nit = it + 1;
        const int nbuf = nit & 1;
        int nh = h, nkc = kc + 1;
        if (nkc == 6) {
            nkc = 0;
            nh = h + 1;
        }

        if (kc == 0) {
#pragma unroll
            for (int i = 0; i < 6; ++i)
#pragma unroll
                for (int j = 0; j < 4; ++j) {
                    accQ[i][j] = 0.f;
                    accK[i][j] = 0.f;
                }
        }

        // issue next-iteration loads (cp.async for A, LDG-to-regs for W) BEFORE MMA
        float pq0[6], pq1[6], pk0[6], pk1[6];
        if (nit < 48) {
            stage_A(sb + nbuf * A_BUF, m0, nbr, tot, r, nkc * KC, tid);
            loadW(Wq, Wk, nh * DHH, nkc * KC, tid, pq0, pq1, pk0, pk1);
        }

        // ---- MMA on current buffer (4 k-steps of 16) ----
#pragma unroll
        for (int ks = 0; ks < 4; ++ks) {
            const uint32_t aoff = aB + a_row * ASTRIDE + (ks * 16 + a_cadd) * 2;
            uint32_t qh0, qh1, qh2, qh3;
            uint32_t kh0, kh1, kh2, kh3;
            ldsm4(aoff + AQH, qh0, qh1, qh2, qh3);
            ldsm4(aoff + AKH, kh0, kh1, kh2, kh3);
#pragma unroll
            for (int ntp = 0; ntp < 3; ++ntp) {
                const uint32_t boff = wB + (ntp * 16 + b_radd) * ASTRIDE + (ks * 16 + b_cadd) * 2;
                uint32_t wq0, wq1, wq2, wq3;
                uint32_t vk0, vk1, vk2, vk3;
                ldsm4(boff + WQH, wq0, wq1, wq2, wq3);
                ldsm4(boff + WKH, vk0, vk1, vk2, vk3);
                mma_f16(accQ[2 * ntp], qh0, qh1, qh2, qh3, wq0, wq1);
                mma_f16(accQ[2 * ntp + 1], qh0, qh1, qh2, qh3, wq2, wq3);
                mma_f16(accK[2 * ntp], kh0, kh1, kh2, kh3, vk0, vk1);
                mma_f16(accK[2 * ntp + 1], kh0, kh1, kh2, kh3, vk2, vk3);
            }
        }

        // ---- epilogue at end of head: diagonal pairing + row sums ----
        if (kc == 5) {
            float sl = 0.f, sh2 = 0.f;
#pragma unroll
            for (int nt = 0; nt < 6; ++nt) {
                sl += accQ[nt][0] * accK[nt][0] + accQ[nt][1] * accK[nt][1];
                sh2 += accQ[nt][2] * accK[nt][2] + accQ[nt][3] * accK[nt][3];
            }
            sl += __shfl_xor_sync(0xffffffffu, sl, 1);
            sl += __shfl_xor_sync(0xffffffffu, sl, 2);
            sh2 += __shfl_xor_sync(0xffffffffu, sh2, 1);
            sh2 += __shfl_xor_sync(0xffffffffu, sh2, 2);
            if ((lane & 3) == 0) {
                const int ur = m0 + wm0 + (lane >> 2);
#pragma unroll
                for (int half = 0; half < 2; ++half) {
                    const int u = ur + half * 8;
                    const float s = half ? sh2 : sl;
                    if (u < tot) {
                        const int b = (u >= nbr);
                        const int t = u - b * nbr;
                        const int ig = r + t;
                        g_dots[(((size_t)b * HH + h) * LL + ig) * LL + t] = s * scale;
                    }
                }
            }
        }

        // convert + store prefetched W into next buffer (after MMA; LDG latency was hidden)
        if (nit < 48) {
            storeW(smem, W_BASE + nbuf * W_BUF, tid, pq0, pq1, pk0, pk1);
        }

        cp_wait_all();
        __syncthreads();
        h = nh;
        kc = nkc;
    }
}

// ======================= causal softmax =======================
__global__ void __launch_bounds__(128) softmax_kernel() {
    const int row = blockIdx.x * 4 + (threadIdx.x >> 5);
    if (row >= BB * HH * LL) return;
    const int lane = threadIdx.x & 31;
    const int i = row % LL;
    float* d = g_dots + (size_t)row * LL;
    const int n = i + 1;
    float mx = -1e30f;
    for (int j = lane; j < n; j += 32) mx = fmaxf(mx, d[j]);
    for (int o = 16; o; o >>= 1) mx = fmaxf(mx, __shfl_xor_sync(0xffffffffu, mx, o));
    float s = 0.f;
    for (int j = lane; j < n; j += 32) {
        float e = __expf(d[j] - mx);
        d[j] = e;
        s += e;
    }
    for (int o = 16; o; o >>= 1) s += __shfl_xor_sync(0xffffffffu, s, o);
    const float inv = 1.f / s;
    for (int j = lane; j < n; j += 32) d[j] *= inv;
}

// ======================= attn @ v =======================
__global__ void __launch_bounds__(192) av_kernel() {
    const int local = threadIdx.x / DHH;
    const int dd = threadIdx.x % DHH;
    const int task = blockIdx.x * 4 + local;
    if (task >= BB * HH * LL) return;
    const int i = task % LL;
    const int bh = task / LL;
    const int h = bh % HH;
    const int b = bh / HH;
    const float* attn = g_dots + (size_t)task * LL;
    const float* vp = g_v + (size_t)b * LL * NN + h * DHH + dd;
    float acc = 0.f;
    for (int j = 0; j <= i; ++j) acc += attn[j] * vp[(size_t)j * NN];
    g_ao[((size_t)b * LL + i) * NN + h * DHH + dd] = acc;
}

// ======================= launcher =======================
extern "C" void kernel_launch(void* const* d_in, const int* in_sizes, int n_in,
                              void* d_out, int out_size) {
    const float* x = (const float*)d_in[0];
    const float* gamma = (const float*)d_in[1];
    const float* beta = (const float*)d_in[2];
    const float* uq = (const float*)d_in[3];
    const float* uk = (const float*)d_in[4];
    const float* wv = (const float*)d_in[5];
    const float* wo = (const float*)d_in[6];
    const float* bo = (const float*)d_in[7];
    float* out = (float*)d_out;

    float* g_xn_p;
    float* g_v_p;
    float* g_ao_p;
    cudaGetSymbolAddress((void**)&g_xn_p, g_xn);
    cudaGetSymbolAddress((void**)&g_v_p, g_v);
    cudaGetSymbolAddress((void**)&g_ao_p, g_ao);
    cudaFuncSetAttribute(dots_mma_kernel, cudaFuncAttributeMaxDynamicSharedMemorySize, SM_TOTAL);

    ln_kernel<<<BB * LL, 128>>>(x, gamma, beta);
    gemm32_kernel<<<dim3(12, 12), 128>>>(g_xn_p, wv, nullptr, g_v_p, 0);
    dots_mma_kernel<<<dim3(3, LL), 256, SM_TOTAL>>>(uq, uk);
    softmax_kernel<<<(BB * HH * LL + 3) / 4, 128>>>();
    av_kernel<<<(BB * HH * LL + 3) / 4, 192>>>();
    gemm32_kernel<<<dim3(12, 12), 128>>>(g_ao_p, wo, bo, out, 1);
}